// round 11
// baseline (speedup 1.0000x reference)
#include <cuda_runtime.h>
#include <cstdint>

// Problem constants (BATCH=4, SEQ=4096, DIM=1024)
#define B 4
#define L 4096
#define D 1024
#define TD 4                  // dim-pair threads (8 dims per block)
#define NCH 64                // chunk threads
#define TPB 256               // TD * NCH
#define DPB 8                 // dims per block
#define CS 16                 // timesteps per chunk
#define SEG (NCH * CS)        // 1024
#define NSEG (L / SEG)        // 4

__device__ __forceinline__ float2 cmul(float2 u, float2 v) {
    return make_float2(fmaf(u.x, v.x, -u.y * v.y), fmaf(u.x, v.y, u.y * v.x));
}

__device__ __forceinline__ float2 decay(float r, float im) {
    float mag = sqrtf(fmaf(r, r, im * im));
    float s = __expf(-mag) / mag;
    return make_float2(r * s, im * s);
}

__global__ void __launch_bounds__(TPB, 3)
spiral_fused2(const float* __restrict__ x,
              const float* __restrict__ pr, const float* __restrict__ pi,
              const float* __restrict__ ir, const float* __restrict__ ii,
              const float* __restrict__ lr, const float* __restrict__ li,
              float* __restrict__ out)
{
    const int dgrp   = blockIdx.x;               // 0..127
    const int b      = blockIdx.y;               // 0..3
    const int dim_id = threadIdx.x & (TD - 1);   // 0..3
    const int chunk  = threadIdx.x >> 2;         // 0..63
    const int d0     = dgrp * DPB + dim_id * 2;

    __shared__ float4 s_val[2][NCH][TD];  // double-buffered chunk scan values
    __shared__ float4 s_pow[6][TD];       // (a^16)^(2^s)
    __shared__ float4 s_E0[TD];           // carried exact state

    const float2 a0 = decay(pr[d0],     pi[d0]);
    const float2 a1 = decay(pr[d0 + 1], pi[d0 + 1]);
    const float2 cre = *(const float2*)(ir + d0);
    const float2 cim = *(const float2*)(ii + d0);

    if (chunk == 0) {
        float2 p0 = a0, p1 = a1;
#pragma unroll
        for (int k = 0; k < 4; k++) { p0 = cmul(p0, p0); p1 = cmul(p1, p1); }  // a^16
#pragma unroll
        for (int s = 0; s < 6; s++) {
            s_pow[s][dim_id] = make_float4(p0.x, p0.y, p1.x, p1.y);
            p0 = cmul(p0, p0); p1 = cmul(p1, p1);
        }
        s_E0[dim_id] = make_float4(lr[b * D + d0], li[b * D + d0],
                                   lr[b * D + d0 + 1], li[b * D + d0 + 1]);
    }
    __syncthreads();

    // w = (a^16)^chunk
    float2 w0 = make_float2(1.f, 0.f), w1 = make_float2(1.f, 0.f);
#pragma unroll
    for (int s = 0; s < 6; s++) {
        if ((chunk >> s) & 1) {
            float4 P = s_pow[s][dim_id];
            w0 = cmul(w0, make_float2(P.x, P.y));
            w1 = cmul(w1, make_float2(P.z, P.w));
        }
    }

#pragma unroll 1
    for (int seg = 0; seg < NSEG; seg++) {
        const size_t base = ((size_t)(b * L + seg * SEG + chunk * CS)) * D + d0;
        const float* xp = x + base;
        float* op = out + base;

        // ---- Load entire chunk into registers (16 independent LDG.64) ----
        float2 xv[CS];
#pragma unroll
        for (int t = 0; t < CS; t++)
            xv[t] = *(const float2*)(xp + (size_t)t * D);

        // ---- Phase 1: zero-init local scan (registers only) ----
        float h0r = 0.f, h0i = 0.f, h1r = 0.f, h1i = 0.f;
#pragma unroll
        for (int t = 0; t < CS; t++) {
            float n0r = fmaf(a0.x, h0r, fmaf(-a0.y, h0i, cre.x * xv[t].x));
            float n0i = fmaf(a0.x, h0i, fmaf( a0.y, h0r, cim.x * xv[t].x));
            float n1r = fmaf(a1.x, h1r, fmaf(-a1.y, h1i, cre.y * xv[t].y));
            float n1i = fmaf(a1.x, h1i, fmaf( a1.y, h1r, cim.y * xv[t].y));
            h0r = n0r; h0i = n0i; h1r = n1r; h1i = n1i;
        }
        float4 val = make_float4(h0r, h0i, h1r, h1i);
        s_val[0][chunk][dim_id] = val;
        __syncthreads();

        // ---- Weighted Hillis-Steele over 64 chunks, 1 barrier/round ----
        int buf = 0;
#pragma unroll
        for (int s = 0; s < 6; s++) {
            float4 o = (chunk >= (1 << s)) ? s_val[buf][chunk - (1 << s)][dim_id]
                                           : make_float4(0.f, 0.f, 0.f, 0.f);
            float4 P = s_pow[s][dim_id];
            val.x = fmaf(P.x, o.x, fmaf(-P.y, o.y, val.x));
            val.y = fmaf(P.x, o.y, fmaf( P.y, o.x, val.y));
            val.z = fmaf(P.z, o.z, fmaf(-P.w, o.w, val.z));
            val.w = fmaf(P.z, o.w, fmaf( P.w, o.z, val.w));
            buf ^= 1;
            s_val[buf][chunk][dim_id] = val;
            __syncthreads();
        }

        // ---- E = w * E0 + val[chunk-1] ----
        float4 E0v = s_E0[dim_id];
        float4 prev = (chunk > 0) ? s_val[buf][chunk - 1][dim_id]
                                  : make_float4(0.f, 0.f, 0.f, 0.f);
        float E0r = fmaf(w0.x, E0v.x, fmaf(-w0.y, E0v.y, prev.x));
        float E0i = fmaf(w0.x, E0v.y, fmaf( w0.y, E0v.x, prev.y));
        float E1r = fmaf(w1.x, E0v.z, fmaf(-w1.y, E0v.w, prev.z));
        float E1i = fmaf(w1.x, E0v.w, fmaf( w1.y, E0v.z, prev.w));
        __syncthreads();

        if (chunk == NCH - 1) {
            float4 P5 = s_pow[5][dim_id];  // (a^16)^32
            float2 c0 = cmul(make_float2(P5.x, P5.y), make_float2(P5.x, P5.y));
            float2 c1 = cmul(make_float2(P5.z, P5.w), make_float2(P5.z, P5.w));
            float4 nE;
            nE.x = fmaf(c0.x, E0v.x, fmaf(-c0.y, E0v.y, val.x));
            nE.y = fmaf(c0.x, E0v.y, fmaf( c0.y, E0v.x, val.y));
            nE.z = fmaf(c1.x, E0v.z, fmaf(-c1.y, E0v.w, val.z));
            nE.w = fmaf(c1.x, E0v.w, fmaf( c1.y, E0v.z, val.w));
            s_E0[dim_id] = nE;
        }

        // ---- Phase 2: exact scan from registers; streaming stores ----
        h0r = E0r; h0i = E0i; h1r = E1r; h1i = E1i;
#pragma unroll
        for (int t = 0; t < CS; t++) {
            float n0r = fmaf(a0.x, h0r, fmaf(-a0.y, h0i, cre.x * xv[t].x));
            float n0i = fmaf(a0.x, h0i, fmaf( a0.y, h0r, cim.x * xv[t].x));
            float n1r = fmaf(a1.x, h1r, fmaf(-a1.y, h1i, cre.y * xv[t].y));
            float n1i = fmaf(a1.x, h1i, fmaf( a1.y, h1r, cim.y * xv[t].y));
            h0r = n0r; h0i = n0i; h1r = n1r; h1i = n1i;
            __stcs((float2*)(op + (size_t)t * D), make_float2(h0r, h1r));
        }
    }
}

extern "C" void kernel_launch(void* const* d_in, const int* in_sizes, int n_in,
                              void* d_out, int out_size) {
    const float* x    = (const float*)d_in[0];
    const float* p_re = (const float*)d_in[1];
    const float* p_im = (const float*)d_in[2];
    const float* i_re = (const float*)d_in[3];
    const float* i_im = (const float*)d_in[4];
    const float* lc_r = (const float*)d_in[5];
    const float* lc_i = (const float*)d_in[6];
    float* out = (float*)d_out;

    dim3 grid(D / DPB, B);   // (128, 4) = 512 blocks x 256 threads
    spiral_fused2<<<grid, TPB>>>(x, p_re, p_im, i_re, i_im, lc_r, lc_i, out);
}